// round 9
// baseline (speedup 1.0000x reference)
#include <cuda_runtime.h>
#include <cuda_fp16.h>
#include <cstdint>

// ---------------------------------------------------------------------------
// Problem constants
// ---------------------------------------------------------------------------
#define TOKENS 8192
#define IN_F   3072
#define OUT_F  8192
#define GROUP  128

// GEMM tiling: 128x128 CTA tile, 2 CTAs/SM (4 warps/SMSP from independent
// CTAs -> decorrelated stalls), 3-stage bulk pipeline, single-buffered
// fragments (register budget 128/thread at occupancy 2 is the hard cap).
#define MT 128
#define NT 128
#define KC 64
#define NKC (IN_F / KC)          // 48
#define STAGES 3
#define A_TILE_BYTES (MT * 128)  // 16384
#define B_TILE_BYTES (NT * 128)  // 16384
#define STAGE_BYTES (A_TILE_BYTES + B_TILE_BYTES)   // 32768
#define SMEM_REQ (1024 + STAGES * STAGE_BYTES + 1024)  // ~100KB -> 2 CTAs/SM

#define MTILES (TOKENS / MT)     // 64
#define NTILES (OUT_F / NT)      // 64

#define XBLOCKS ((TOKENS * (IN_F / 8)) / 256)   // 12288
#define WBLOCKS ((OUT_F * (IN_F / 8)) / 256)    // 12288

// ---------------------------------------------------------------------------
// Static device scratch: pre-tiled, pre-SW128-swizzled fp16 operands.
// Blocks of 128 rows x 64 halves; element (r,k) at byte swz128(r*128+k*2).
// ---------------------------------------------------------------------------
__device__ __align__(1024) __half g_X[(size_t)TOKENS * IN_F];
__device__ __align__(1024) __half g_W[(size_t)OUT_F * IN_F];

__device__ __forceinline__ uint32_t swz128(uint32_t b) { return b ^ ((b >> 3) & 0x70); }

// ---------------------------------------------------------------------------
// Fused preprocess: first XBLOCKS blocks convert x, rest dequantize W.
// ---------------------------------------------------------------------------
__global__ void preproc_kernel(const float* __restrict__ x,
                               const int* __restrict__ pk,
                               const float* __restrict__ sc) {
    uint32_t b = blockIdx.x;
    if (b < XBLOCKS) {
        uint32_t idx = b * blockDim.x + threadIdx.x;
        uint32_t m = idx / (IN_F / 8);
        uint32_t g = idx % (IN_F / 8);
        const float4* src = reinterpret_cast<const float4*>(x + (size_t)m * IN_F + (size_t)g * 8);
        float4 a = src[0];
        float4 c = src[1];
        __half2 h0 = __floats2half2_rn(a.x, a.y);
        __half2 h1 = __floats2half2_rn(a.z, a.w);
        __half2 h2 = __floats2half2_rn(c.x, c.y);
        __half2 h3 = __floats2half2_rn(c.z, c.w);
        uint4 v;
        v.x = *reinterpret_cast<uint32_t*>(&h0);
        v.y = *reinterpret_cast<uint32_t*>(&h1);
        v.z = *reinterpret_cast<uint32_t*>(&h2);
        v.w = *reinterpret_cast<uint32_t*>(&h3);
        uint32_t t = m / MT, r = m % MT, cc = g / 8, kk = (g % 8) * 8;
        char* base = reinterpret_cast<char*>(g_X) + ((size_t)t * NKC + cc) * A_TILE_BYTES;
        *reinterpret_cast<uint4*>(base + swz128(r * 128 + kk * 2)) = v;
    } else {
        uint32_t idx = (b - XBLOCKS) * blockDim.x + threadIdx.x;
        uint32_t o = idx / (IN_F / 8);
        uint32_t g = idx % (IN_F / 8);
        uint4 p = *reinterpret_cast<const uint4*>(pk + (size_t)o * (IN_F / 2) + (size_t)g * 4);
        float s = sc[(size_t)o * (IN_F / GROUP) + (g / 16)];
        uint32_t w[4] = {p.x, p.y, p.z, p.w};
        uint32_t res[4];
#pragma unroll
        for (int i = 0; i < 4; i++) {
            uint32_t byte = w[i] & 0xFFu;
            int ev = (int)((byte & 15u) ^ 8u) - 8;
            int od = (int)(((byte >> 4) & 15u) ^ 8u) - 8;
            __half2 h = __floats2half2_rn(s * (float)ev, s * (float)od);
            res[i] = *reinterpret_cast<uint32_t*>(&h);
        }
        uint4 v; v.x = res[0]; v.y = res[1]; v.z = res[2]; v.w = res[3];
        uint32_t t = o / NT, r = o % NT, cc = g / 8, kk = (g % 8) * 8;
        char* base = reinterpret_cast<char*>(g_W) + ((size_t)t * NKC + cc) * B_TILE_BYTES;
        *reinterpret_cast<uint4*>(base + swz128(r * 128 + kk * 2)) = v;
    }
}

// ---------------------------------------------------------------------------
// PTX helpers
// ---------------------------------------------------------------------------
__device__ __forceinline__ uint32_t smem_u32(const void* p) {
    uint32_t a;
    asm("{ .reg .u64 t; cvta.to.shared.u64 t, %1; cvt.u32.u64 %0, t; }" : "=r"(a) : "l"(p));
    return a;
}
#define MBAR_INIT(a, c) \
    asm volatile("mbarrier.init.shared.b64 [%0], %1;" :: "r"(a), "r"(c) : "memory")
#define MBAR_EXPECT_TX(a, n) \
    asm volatile("mbarrier.arrive.expect_tx.shared.b64 _, [%0], %1;" :: "r"(a), "r"(n) : "memory")
#define MBAR_ARRIVE(a) \
    asm volatile("mbarrier.arrive.shared.b64 _, [%0];" :: "r"(a) : "memory")
#define MBAR_WAIT(addr, ph) do {                                                        \
    uint32_t _m = (addr); uint32_t _p = (ph); uint32_t _d;                              \
    asm volatile("{\n\t.reg .pred p;\n\t"                                               \
        "mbarrier.try_wait.parity.acquire.cta.shared::cta.b64 p, [%1], %2;\n\t"         \
        "selp.b32 %0, 1, 0, p;\n\t}"                                                    \
        : "=r"(_d) : "r"(_m), "r"(_p) : "memory");                                      \
    if (!_d) {                                                                          \
        asm volatile("{\n\t.reg .pred P1;\n\t"                                          \
            "WL%=:\n\t"                                                                 \
            "mbarrier.try_wait.parity.acquire.cta.shared::cta.b64 P1, [%0], %1, 0x989680;\n\t" \
            "@P1 bra.uni WD%=;\n\t"                                                     \
            "bra.uni WL%=;\n\t"                                                         \
            "WD%=:\n\t}"                                                                \
            :: "r"(_m), "r"(_p) : "memory");                                            \
    }                                                                                   \
} while (0)

__device__ __forceinline__ void bulk_g2s(uint32_t dst, const void* src, uint32_t bytes, uint32_t mbar) {
    asm volatile(
        "cp.async.bulk.shared::cluster.global.mbarrier::complete_tx::bytes [%0], [%1], %2, [%3];"
        :: "r"(dst), "l"(src), "r"(bytes), "r"(mbar) : "memory");
}

#define LDSM_X4(R, addr)                                                               \
    asm volatile("ldmatrix.sync.aligned.m8n8.x4.shared.b16 {%0,%1,%2,%3}, [%4];"       \
        : "=r"((R)[0]), "=r"((R)[1]), "=r"((R)[2]), "=r"((R)[3]) : "r"(addr))

#define MMA16816(C, A, B0, B1)                                                          \
    asm volatile("mma.sync.aligned.m16n8k16.row.col.f32.f16.f16.f32 "                   \
        "{%0,%1,%2,%3}, {%4,%5,%6,%7}, {%8,%9}, {%0,%1,%2,%3};"                         \
        : "+f"((C)[0]), "+f"((C)[1]), "+f"((C)[2]), "+f"((C)[3])                        \
        : "r"((A)[0]), "r"((A)[1]), "r"((A)[2]), "r"((A)[3]), "r"(B0), "r"(B1))

// ---------------------------------------------------------------------------
// GEMM: 128x128 CTA tile, 8 warps (2M x 4N, warp tile 64x32), 3-stage
// pipeline, 2 CTAs/SM, rotated non-blocking producer, lid0 empty-arrives.
// ---------------------------------------------------------------------------
__global__ void __launch_bounds__(256, 2) gemm_kernel(float* __restrict__ out,
                                                      const float* __restrict__ bias) {
    extern __shared__ char smem_raw[];
    char* sbp = (char*)(((uintptr_t)smem_raw + 1023) & ~(uintptr_t)1023);
    const uint32_t SB  = smem_u32(sbp);
    const uint32_t BAR = SB + STAGES * STAGE_BYTES;      // full[s]@+16s, empty[s]@+16s+8
    float* bias_s = reinterpret_cast<float*>(sbp + STAGES * STAGE_BYTES + 256);

    const int tid = threadIdx.x;
    const int wid = tid >> 5;
    const int lid = tid & 31;
    const int wm = wid >> 2;       // 0..1  (64 rows each)
    const int wn = wid & 3;        // 0..3  (32 cols each)

    // supertile rasterization: 16 m-tiles x 64 n-tiles per super-row
    const int bid = blockIdx.x;
    const int sr  = bid >> 10;                // 4 super rows
    const int rem = bid & 1023;
    const int m_tile = (sr << 4) | (rem & 15);
    const int n_tile = rem >> 4;

    if (tid == 0) {
#pragma unroll
        for (int s = 0; s < STAGES; s++) {
            MBAR_INIT(BAR + s * 16, 1);      // full: expect_tx arrive + tx
            MBAR_INIT(BAR + s * 16 + 8, 8);  // empty: one arrive per warp
        }
    }
    if (tid < NT) bias_s[tid] = bias[n_tile * NT + tid];
    __syncthreads();

    const char* gA = (const char*)g_X + (size_t)m_tile * NKC * A_TILE_BYTES;
    const char* gB = (const char*)g_W + (size_t)n_tile * NKC * B_TILE_BYTES;

    // prologue: fill stages 0..1 (stage 2 filled at end of chunk 0, no wait)
    if (tid == 0) {
#pragma unroll
        for (int c = 0; c < STAGES - 1; c++) {
            MBAR_EXPECT_TX(BAR + c * 16, (uint32_t)STAGE_BYTES);
            bulk_g2s(SB + c * STAGE_BYTES, gA + (size_t)c * A_TILE_BYTES,
                     A_TILE_BYTES, BAR + c * 16);
            bulk_g2s(SB + c * STAGE_BYTES + A_TILE_BYTES, gB + (size_t)c * B_TILE_BYTES,
                     B_TILE_BYTES, BAR + c * 16);
        }
    }

    // per-thread ldmatrix address components (swizzle XOR folded)
    const int l16 = lid & 15;
    const uint32_t half16 = (uint32_t)(lid >> 4) * 16;
    uint32_t arow[4], axm[4], brow[2], bxm[2];
#pragma unroll
    for (int i = 0; i < 4; i++) {
        uint32_t ra = (uint32_t)(wm * 64 + i * 16 + l16);
        arow[i] = ra * 128;
        axm[i] = (ra & 7) << 4;
    }
#pragma unroll
    for (int i = 0; i < 2; i++) {
        uint32_t rb = (uint32_t)(wn * 32 + i * 16 + l16);
        brow[i] = rb * 128;
        bxm[i] = (rb & 7) << 4;
    }

    float acc[4][4][4];
#pragma unroll
    for (int mi = 0; mi < 4; mi++)
#pragma unroll
        for (int ni = 0; ni < 4; ni++)
#pragma unroll
            for (int q = 0; q < 4; q++) acc[mi][ni][q] = 0.0f;

    int s = 0;
    uint32_t ph = 0;
    for (int c = 0; c < NKC; c++) {
        MBAR_WAIT(BAR + s * 16, ph);
        const uint32_t As = SB + s * STAGE_BYTES;
        const uint32_t Bs = As + A_TILE_BYTES;

#pragma unroll
        for (int kk = 0; kk < 4; kk++) {
            const uint32_t kb = (uint32_t)kk * 32 + half16;
            uint32_t a[4][4], b[2][4];
#pragma unroll
            for (int mi = 0; mi < 4; mi++) LDSM_X4(a[mi], As + arow[mi] + (kb ^ axm[mi]));
#pragma unroll
            for (int nj = 0; nj < 2; nj++) LDSM_X4(b[nj], Bs + brow[nj] + (kb ^ bxm[nj]));
#pragma unroll
            for (int mi = 0; mi < 4; mi++) {
#pragma unroll
                for (int nj = 0; nj < 2; nj++) {
                    MMA16816(acc[mi][2 * nj],     a[mi], b[nj][0], b[nj][2]);
                    MMA16816(acc[mi][2 * nj + 1], a[mi], b[nj][1], b[nj][3]);
                }
            }
        }

        // stage s fully consumed into registers
        if (lid == 0) MBAR_ARRIVE(BAR + s * 16 + 8);

        // producer (rotated warp c&7, lane 0): refill chunk c+2 into the stage
        // freed at the end of chunk c-1 -> empty wait is (nearly) fast-path.
        if (wid == (c & 7) && lid == 0 && c + STAGES - 1 < NKC) {
            const int cp = c + STAGES - 1;          // chunk to load
            const int sp = cp - (cp / STAGES) * STAGES;
            if (c >= 1) {
                // empty[sp] last armed at end of chunk c-1; completion count
                // so far = floor((c-1)/3)+1 -> wait parity floor((c-1)/3)&1
                MBAR_WAIT(BAR + sp * 16 + 8, (uint32_t)(((c - 1) / STAGES) & 1));
            }
            MBAR_EXPECT_TX(BAR + sp * 16, (uint32_t)STAGE_BYTES);
            bulk_g2s(SB + sp * STAGE_BYTES, gA + (size_t)cp * A_TILE_BYTES,
                     A_TILE_BYTES, BAR + sp * 16);
            bulk_g2s(SB + sp * STAGE_BYTES + A_TILE_BYTES,
                     gB + (size_t)cp * B_TILE_BYTES,
                     B_TILE_BYTES, BAR + sp * 16);
        }

        if (++s == STAGES) { s = 0; ph ^= 1; }
    }

    // epilogue: direct register -> gmem with bias
    const int row_in_tile = lid >> 2;
    const int col_pair = (lid & 3) * 2;
    const size_t mbase = (size_t)m_tile * MT + wm * 64;
    const size_t nbase = (size_t)n_tile * NT;
#pragma unroll
    for (int mi = 0; mi < 4; mi++) {
        const size_t m0 = mbase + mi * 16 + row_in_tile;
#pragma unroll
        for (int ni = 0; ni < 4; ni++) {
            const int nloc = wn * 32 + ni * 8 + col_pair;
            const float b0 = bias_s[nloc];
            const float b1 = bias_s[nloc + 1];
            float2 v0 = make_float2(acc[mi][ni][0] + b0, acc[mi][ni][1] + b1);
            float2 v1 = make_float2(acc[mi][ni][2] + b0, acc[mi][ni][3] + b1);
            *reinterpret_cast<float2*>(out + m0 * OUT_F + nbase + nloc) = v0;
            *reinterpret_cast<float2*>(out + (m0 + 8) * OUT_F + nbase + nloc) = v1;
        }
    }
}

// ---------------------------------------------------------------------------
// Launch
// ---------------------------------------------------------------------------
extern "C" void kernel_launch(void* const* d_in, const int* in_sizes, int n_in,
                              void* d_out, int out_size) {
    (void)in_sizes; (void)n_in; (void)out_size;
    const float* x    = (const float*)d_in[0];
    const int*   pk   = (const int*)d_in[1];
    const float* sc   = (const float*)d_in[2];
    const float* bias = (const float*)d_in[3];
    float* out = (float*)d_out;

    cudaFuncSetAttribute(gemm_kernel, cudaFuncAttributeMaxDynamicSharedMemorySize, SMEM_REQ);

    preproc_kernel<<<XBLOCKS + WBLOCKS, 256>>>(x, pk, sc);
    gemm_kernel<<<MTILES * NTILES, 256, SMEM_REQ>>>(out, bias);
}

// round 10
// speedup vs baseline: 1.1062x; 1.1062x over previous
#include <cuda_runtime.h>
#include <cuda_fp16.h>
#include <cstdint>

// ---------------------------------------------------------------------------
// Problem constants
// ---------------------------------------------------------------------------
#define TOKENS 8192
#define IN_F   3072
#define OUT_F  8192
#define GROUP  128

// GEMM tiling: 128x256 CTA tile, 8 warps (2M x 4N, warp tile 64x64),
// 4-stage bulk pipeline, fragment double-buffering, and (round 10) per-warp
// k-step rotation: warps 4-7 process each chunk's k-steps in order 2,3,0,1 so
// the two warps sharing an SMSP are anti-phased (LDSM burst of one overlaps
// MMA stream of the other).
#define MT 128
#define NT 256
#define KC 64
#define NKC (IN_F / KC)          // 48
#define STAGES 4
#define A_TILE_BYTES (MT * 128)  // 16384
#define B_TILE_BYTES (NT * 128)  // 32768
#define STAGE_BYTES (A_TILE_BYTES + B_TILE_BYTES)   // 49152
#define SMEM_REQ (1024 + STAGES * STAGE_BYTES + 1024)  // ~198KB, 1 CTA/SM

#define MTILES (TOKENS / MT)     // 64
#define NTILES (OUT_F / NT)      // 32

#define XBLOCKS ((TOKENS * (IN_F / 8)) / 256)   // 12288
#define WBLOCKS ((OUT_F * (IN_F / 8)) / 256)    // 12288

// ---------------------------------------------------------------------------
// Static device scratch: pre-tiled, pre-SW128-swizzled fp16 operands.
// ---------------------------------------------------------------------------
__device__ __align__(1024) __half g_X[(size_t)TOKENS * IN_F];
__device__ __align__(1024) __half g_W[(size_t)OUT_F * IN_F];

__device__ __forceinline__ uint32_t swz128(uint32_t b) { return b ^ ((b >> 3) & 0x70); }

// ---------------------------------------------------------------------------
// Fused preprocess: first XBLOCKS blocks convert x, rest dequantize W.
// ---------------------------------------------------------------------------
__global__ void preproc_kernel(const float* __restrict__ x,
                               const int* __restrict__ pk,
                               const float* __restrict__ sc) {
    uint32_t b = blockIdx.x;
    if (b < XBLOCKS) {
        uint32_t idx = b * blockDim.x + threadIdx.x;
        uint32_t m = idx / (IN_F / 8);
        uint32_t g = idx % (IN_F / 8);
        const float4* src = reinterpret_cast<const float4*>(x + (size_t)m * IN_F + (size_t)g * 8);
        float4 a = src[0];
        float4 c = src[1];
        __half2 h0 = __floats2half2_rn(a.x, a.y);
        __half2 h1 = __floats2half2_rn(a.z, a.w);
        __half2 h2 = __floats2half2_rn(c.x, c.y);
        __half2 h3 = __floats2half2_rn(c.z, c.w);
        uint4 v;
        v.x = *reinterpret_cast<uint32_t*>(&h0);
        v.y = *reinterpret_cast<uint32_t*>(&h1);
        v.z = *reinterpret_cast<uint32_t*>(&h2);
        v.w = *reinterpret_cast<uint32_t*>(&h3);
        uint32_t t = m / MT, r = m % MT, cc = g / 8, kk = (g % 8) * 8;
        char* base = reinterpret_cast<char*>(g_X) + ((size_t)t * NKC + cc) * A_TILE_BYTES;
        *reinterpret_cast<uint4*>(base + swz128(r * 128 + kk * 2)) = v;
    } else {
        uint32_t idx = (b - XBLOCKS) * blockDim.x + threadIdx.x;
        uint32_t o = idx / (IN_F / 8);
        uint32_t g = idx % (IN_F / 8);
        uint4 p = *reinterpret_cast<const uint4*>(pk + (size_t)o * (IN_F / 2) + (size_t)g * 4);
        float s = sc[(size_t)o * (IN_F / GROUP) + (g / 16)];
        uint32_t w[4] = {p.x, p.y, p.z, p.w};
        uint32_t res[4];
#pragma unroll
        for (int i = 0; i < 4; i++) {
            uint32_t byte = w[i] & 0xFFu;
            int ev = (int)((byte & 15u) ^ 8u) - 8;
            int od = (int)(((byte >> 4) & 15u) ^ 8u) - 8;
            __half2 h = __floats2half2_rn(s * (float)ev, s * (float)od);
            res[i] = *reinterpret_cast<uint32_t*>(&h);
        }
        uint4 v; v.x = res[0]; v.y = res[1]; v.z = res[2]; v.w = res[3];
        uint32_t t = o / NT, r = o % NT, cc = g / 8, kk = (g % 8) * 8;
        char* base = reinterpret_cast<char*>(g_W) + ((size_t)t * NKC + cc) * B_TILE_BYTES;
        *reinterpret_cast<uint4*>(base + swz128(r * 128 + kk * 2)) = v;
    }
}

// ---------------------------------------------------------------------------
// PTX helpers
// ---------------------------------------------------------------------------
__device__ __forceinline__ uint32_t smem_u32(const void* p) {
    uint32_t a;
    asm("{ .reg .u64 t; cvta.to.shared.u64 t, %1; cvt.u32.u64 %0, t; }" : "=r"(a) : "l"(p));
    return a;
}
#define MBAR_INIT(a, c) \
    asm volatile("mbarrier.init.shared.b64 [%0], %1;" :: "r"(a), "r"(c) : "memory")
#define MBAR_EXPECT_TX(a, n) \
    asm volatile("mbarrier.arrive.expect_tx.shared.b64 _, [%0], %1;" :: "r"(a), "r"(n) : "memory")
#define MBAR_ARRIVE(a) \
    asm volatile("mbarrier.arrive.shared.b64 _, [%0];" :: "r"(a) : "memory")
#define MBAR_WAIT(addr, ph) do {                                                        \
    uint32_t _m = (addr); uint32_t _p = (ph); uint32_t _d;                              \
    asm volatile("{\n\t.reg .pred p;\n\t"                                               \
        "mbarrier.try_wait.parity.acquire.cta.shared::cta.b64 p, [%1], %2;\n\t"         \
        "selp.b32 %0, 1, 0, p;\n\t}"                                                    \
        : "=r"(_d) : "r"(_m), "r"(_p) : "memory");                                      \
    if (!_d) {                                                                          \
        asm volatile("{\n\t.reg .pred P1;\n\t"                                          \
            "WL%=:\n\t"                                                                 \
            "mbarrier.try_wait.parity.acquire.cta.shared::cta.b64 P1, [%0], %1, 0x989680;\n\t" \
            "@P1 bra.uni WD%=;\n\t"                                                     \
            "bra.uni WL%=;\n\t"                                                         \
            "WD%=:\n\t}"                                                                \
            :: "r"(_m), "r"(_p) : "memory");                                            \
    }                                                                                   \
} while (0)

__device__ __forceinline__ void bulk_g2s(uint32_t dst, const void* src, uint32_t bytes, uint32_t mbar) {
    asm volatile(
        "cp.async.bulk.shared::cluster.global.mbarrier::complete_tx::bytes [%0], [%1], %2, [%3];"
        :: "r"(dst), "l"(src), "r"(bytes), "r"(mbar) : "memory");
}

#define LDSM_X4(R, addr)                                                               \
    asm volatile("ldmatrix.sync.aligned.m8n8.x4.shared.b16 {%0,%1,%2,%3}, [%4];"       \
        : "=r"((R)[0]), "=r"((R)[1]), "=r"((R)[2]), "=r"((R)[3]) : "r"(addr))

#define MMA16816(C, A, B0, B1)                                                          \
    asm volatile("mma.sync.aligned.m16n8k16.row.col.f32.f16.f16.f32 "                   \
        "{%0,%1,%2,%3}, {%4,%5,%6,%7}, {%8,%9}, {%0,%1,%2,%3};"                         \
        : "+f"((C)[0]), "+f"((C)[1]), "+f"((C)[2]), "+f"((C)[3])                        \
        : "r"((A)[0]), "r"((A)[1]), "r"((A)[2]), "r"((A)[3]), "r"(B0), "r"(B1))

// ---------------------------------------------------------------------------
// GEMM: 128x256 CTA, 8 warps (2M x 4N, warp tile 64x64), 4-stage pipeline,
// fragment double-buffering + anti-phased k-step order between SMSP partners.
// ---------------------------------------------------------------------------
__global__ void __launch_bounds__(256, 1) gemm_kernel(float* __restrict__ out,
                                                      const float* __restrict__ bias) {
    extern __shared__ char smem_raw[];
    char* sbp = (char*)(((uintptr_t)smem_raw + 1023) & ~(uintptr_t)1023);
    const uint32_t SB  = smem_u32(sbp);
    const uint32_t BAR = SB + STAGES * STAGE_BYTES;      // full[s]@+16s, empty[s]@+16s+8
    float* bias_s = reinterpret_cast<float*>(sbp + STAGES * STAGE_BYTES + 256);

    const int tid = threadIdx.x;
    const int wid = tid >> 5;
    const int lid = tid & 31;
    const int wm = wid >> 2;       // 0..1 (64 rows); also SMSP-partner parity
    const int wn = wid & 3;        // 0..3 (64 cols)
    // k-step phase rotation: warps {0..3} start at k-step 0, warps {4..7}
    // (their SMSP partners) start at k-step 2 -> anti-phased LDSM bursts.
    const uint32_t kph = (uint32_t)(wm * 2);

    // supertile rasterization: 16 m-tiles x 32 n-tiles per super-row
    const int bid = blockIdx.x;
    const int sr  = bid >> 9;
    const int rem = bid & 511;
    const int m_tile = (sr << 4) | (rem & 15);
    const int n_tile = rem >> 4;

    if (tid == 0) {
#pragma unroll
        for (int s = 0; s < STAGES; s++) {
            MBAR_INIT(BAR + s * 16, 1);      // full: expect_tx arrive + tx
            MBAR_INIT(BAR + s * 16 + 8, 8);  // empty: one arrive per warp
        }
    }
    bias_s[tid] = bias[n_tile * NT + tid];
    __syncthreads();

    const char* gA = (const char*)g_X + (size_t)m_tile * NKC * A_TILE_BYTES;
    const char* gB = (const char*)g_W + (size_t)n_tile * NKC * B_TILE_BYTES;

    // prologue: fill stages 0..2 (stage 3 filled at end of chunk 0)
    if (tid == 0) {
#pragma unroll
        for (int c = 0; c < STAGES - 1; c++) {
            MBAR_EXPECT_TX(BAR + c * 16, (uint32_t)STAGE_BYTES);
            bulk_g2s(SB + c * STAGE_BYTES, gA + (size_t)c * A_TILE_BYTES,
                     A_TILE_BYTES, BAR + c * 16);
            bulk_g2s(SB + c * STAGE_BYTES + A_TILE_BYTES, gB + (size_t)c * B_TILE_BYTES,
                     B_TILE_BYTES, BAR + c * 16);
        }
    }

    // per-thread ldmatrix address components
    const int l16 = lid & 15;
    const uint32_t half16 = (uint32_t)(lid >> 4) * 16;
    uint32_t arow[4], axm[4], brow[4], bxm[4];
#pragma unroll
    for (int i = 0; i < 4; i++) {
        uint32_t ra = (uint32_t)(wm * 64 + i * 16 + l16);
        arow[i] = ra * 128;
        axm[i] = (ra & 7) << 4;
        uint32_t rb = (uint32_t)(wn * 64 + i * 16 + l16);
        brow[i] = rb * 128;
        bxm[i] = (rb & 7) << 4;
    }

    float acc[4][8][4];
#pragma unroll
    for (int mi = 0; mi < 4; mi++)
#pragma unroll
        for (int ni = 0; ni < 8; ni++)
#pragma unroll
            for (int q = 0; q < 4; q++) acc[mi][ni][q] = 0.0f;

    uint32_t a[2][4][4], b[2][4][4];

    // wait stage 0 full, prefetch chunk-0 k-step kph into buf 0
    MBAR_WAIT(BAR + 0, 0);
    {
        const uint32_t As = SB, Bs = SB + A_TILE_BYTES;
        const uint32_t kb = kph * 32 + half16;
#pragma unroll
        for (int mi = 0; mi < 4; mi++) LDSM_X4(a[0][mi], As + arow[mi] + (kb ^ axm[mi]));
#pragma unroll
        for (int nj = 0; nj < 4; nj++) LDSM_X4(b[0][nj], Bs + brow[nj] + (kb ^ bxm[nj]));
    }

    int s = 0;
    for (int c = 0; c < NKC; c++) {
        const uint32_t As = SB + s * STAGE_BYTES;
        const uint32_t Bs = As + A_TILE_BYTES;
        const int s2 = (s + 1) & (STAGES - 1);

#pragma unroll
        for (int j = 0; j < 4; j++) {
            const int cur = j & 1, nxt = cur ^ 1;
            if (j < 3) {
                // prefetch this chunk's next k-step (rotated order)
                const uint32_t kq = (uint32_t)((j + 1 + kph) & 3);
                const uint32_t kb = kq * 32 + half16;
#pragma unroll
                for (int mi = 0; mi < 4; mi++) LDSM_X4(a[nxt][mi], As + arow[mi] + (kb ^ axm[mi]));
#pragma unroll
                for (int nj = 0; nj < 4; nj++) LDSM_X4(b[nxt][nj], Bs + brow[nj] + (kb ^ bxm[nj]));
            } else if (c + 1 < NKC) {
                // chunk boundary: wait next stage full, fetch its k-step kph
                MBAR_WAIT(BAR + s2 * 16, (uint32_t)(((c + 1) >> 2) & 1));
                const uint32_t As2 = SB + s2 * STAGE_BYTES;
                const uint32_t Bs2 = As2 + A_TILE_BYTES;
                const uint32_t kb = kph * 32 + half16;
#pragma unroll
                for (int mi = 0; mi < 4; mi++) LDSM_X4(a[nxt][mi], As2 + arow[mi] + (kb ^ axm[mi]));
#pragma unroll
                for (int nj = 0; nj < 4; nj++) LDSM_X4(b[nxt][nj], Bs2 + brow[nj] + (kb ^ bxm[nj]));
            }
#pragma unroll
            for (int mi = 0; mi < 4; mi++) {
#pragma unroll
                for (int nj = 0; nj < 4; nj++) {
                    MMA16816(acc[mi][2 * nj],     a[cur][mi], b[cur][nj][0], b[cur][nj][2]);
                    MMA16816(acc[mi][2 * nj + 1], a[cur][mi], b[cur][nj][1], b[cur][nj][3]);
                }
            }
        }

        // stage s fully consumed into registers
        if (lid == 0) MBAR_ARRIVE(BAR + s * 16 + 8);

        // producer (rotated: warp c&7, lane 0): refill chunk c+3 into the stage
        // freed last chunk (empty barrier already complete -> fast path)
        if (wid == (c & 7) && lid == 0 && c + STAGES - 1 < NKC) {
            const int cp = c + STAGES - 1;
            const int sp = cp & (STAGES - 1);
            if (c >= 1) MBAR_WAIT(BAR + sp * 16 + 8, (uint32_t)(((c - 1) >> 2) & 1));
            MBAR_EXPECT_TX(BAR + sp * 16, (uint32_t)STAGE_BYTES);
            bulk_g2s(SB + sp * STAGE_BYTES, gA + (size_t)cp * A_TILE_BYTES,
                     A_TILE_BYTES, BAR + sp * 16);
            bulk_g2s(SB + sp * STAGE_BYTES + A_TILE_BYTES,
                     gB + (size_t)cp * B_TILE_BYTES,
                     B_TILE_BYTES, BAR + sp * 16);
        }

        s = s2;
    }

    // epilogue: direct register -> gmem with bias
    const int row_in_tile = lid >> 2;
    const int col_pair = (lid & 3) * 2;
    const size_t mbase = (size_t)m_tile * MT + wm * 64;
    const size_t nbase = (size_t)n_tile * NT;
#pragma unroll
    for (int mi = 0; mi < 4; mi++) {
        const size_t m0 = mbase + mi * 16 + row_in_tile;
#pragma unroll
        for (int ni = 0; ni < 8; ni++) {
            const int nloc = wn * 64 + ni * 8 + col_pair;
            const float b0 = bias_s[nloc];
            const float b1 = bias_s[nloc + 1];
            float2 v0 = make_float2(acc[mi][ni][0] + b0, acc[mi][ni][1] + b1);
            float2 v1 = make_float2(acc[mi][ni][2] + b0, acc[mi][ni][3] + b1);
            *reinterpret_cast<float2*>(out + m0 * OUT_F + nbase + nloc) = v0;
            *reinterpret_cast<float2*>(out + (m0 + 8) * OUT_F + nbase + nloc) = v1;
        }
    }
}

// ---------------------------------------------------------------------------
// Launch
// ---------------------------------------------------------------------------
extern "C" void kernel_launch(void* const* d_in, const int* in_sizes, int n_in,
                              void* d_out, int out_size) {
    (void)in_sizes; (void)n_in; (void)out_size;
    const float* x    = (const float*)d_in[0];
    const int*   pk   = (const int*)d_in[1];
    const float* sc   = (const float*)d_in[2];
    const float* bias = (const float*)d_in[3];
    float* out = (float*)d_out;

    cudaFuncSetAttribute(gemm_kernel, cudaFuncAttributeMaxDynamicSharedMemorySize, SMEM_REQ);

    preproc_kernel<<<XBLOCKS + WBLOCKS, 256>>>(x, pk, sc);
    gemm_kernel<<<MTILES * NTILES, 256, SMEM_REQ>>>(out, bias);
}